// round 2
// baseline (speedup 1.0000x reference)
#include <cuda_runtime.h>

#define SEQ   600
#define TOUT  594   // SEQ - P
#define PP    6
#define KD    7
#define NWA   8     // warps (rows) per block in solve kernel
#define ROWPAD 608
#define MAXN  32768

// lower-triangular index, r >= c
#define LT(r, c) ((r) * ((r) + 1) / 2 + (c))
// upper-tri (k<=l) packed index used by G accumulation
#define GU(k, l) ((k) * KD - (k) * ((k) - 1) / 2 + ((l) - (k)))

__device__ float g_w[MAXN * 8];

// ============================================================
// Kernel A: per-row AR(6) normal equations + fp64 Cholesky solve
// ============================================================
__global__ __launch_bounds__(NWA * 32, 4)
void solve_kernel(const float* __restrict__ x, int N) {
    __shared__ float  sh[NWA][ROWPAD];
    __shared__ double shL[NWA][28];   // lower-tri Cholesky workspace
    __shared__ double shB[NWA][KD];   // rhs / solution workspace

    const int warp = threadIdx.x >> 5;
    const int lane = threadIdx.x & 31;
    const int row  = blockIdx.x * NWA + warp;
    if (row >= N) return;

    // ---- Load row (150 float4) into shared, coalesced ----
    const float4* xv = (const float4*)(x + (size_t)row * SEQ);
    float4* sv = (float4*)sh[warp];
    #pragma unroll
    for (int i = 0; i < 5; i++) {
        int j = lane + i * 32;
        if (j < 150) sv[j] = xv[j];
    }
    __syncwarp();
    const float* s = sh[warp];

    // ---- Accumulate G (28 upper-tri) and b (7) ----
    float G[28], bb[KD];
    #pragma unroll
    for (int i = 0; i < 28; i++) G[i] = 0.f;
    #pragma unroll
    for (int i = 0; i < KD; i++) bb[i] = 0.f;

    for (int t = lane; t < TOUT; t += 32) {
        float d[KD];
        d[0] = 1.f;
        d[1] = s[t + 5];
        d[2] = s[t + 4];
        d[3] = s[t + 3];
        d[4] = s[t + 2];
        d[5] = s[t + 1];
        d[6] = s[t + 0];
        const float y = s[t + 6];
        int idx = 0;
        #pragma unroll
        for (int k = 0; k < KD; k++) {
            #pragma unroll
            for (int l = k; l < KD; l++) {
                G[idx] = fmaf(d[k], d[l], G[idx]);
                idx++;
            }
            bb[k] = fmaf(d[k], y, bb[k]);
        }
    }

    // ---- Warp butterfly reduction ----
    #pragma unroll
    for (int i = 0; i < 28; i++) {
        #pragma unroll
        for (int o = 16; o > 0; o >>= 1)
            G[i] += __shfl_xor_sync(0xffffffffu, G[i], o);
    }
    #pragma unroll
    for (int i = 0; i < KD; i++) {
        #pragma unroll
        for (int o = 16; o > 0; o >>= 1)
            bb[i] += __shfl_xor_sync(0xffffffffu, bb[i], o);
    }

    // ---- Lane 0: fp64 Cholesky solve in SHARED (keeps regs low) ----
    if (lane == 0) {
        double* L = shL[warp];
        double* B = shB[warp];
        // A(lower)[r][c] = G(c, r) for r >= c
        #pragma unroll
        for (int c = 0; c < KD; c++)
            #pragma unroll
            for (int r = c; r < KD; r++)
                L[LT(r, c)] = (double)G[GU(c, r)];
        #pragma unroll
        for (int k = 0; k < KD; k++) B[k] = (double)bb[k];

        // Cholesky: L <- chol(A)
        #pragma unroll
        for (int c = 0; c < KD; c++) {
            double sd = L[LT(c, c)];
            #pragma unroll
            for (int k = 0; k < c; k++) sd -= L[LT(c, k)] * L[LT(c, k)];
            double lcc = sqrt(sd);
            L[LT(c, c)] = lcc;
            double inv = 1.0 / lcc;
            #pragma unroll
            for (int r = c + 1; r < KD; r++) {
                double s2 = L[LT(r, c)];
                #pragma unroll
                for (int k = 0; k < c; k++) s2 -= L[LT(r, k)] * L[LT(c, k)];
                L[LT(r, c)] = s2 * inv;
            }
        }
        // Forward solve L z = b   (in place in B)
        #pragma unroll
        for (int r = 0; r < KD; r++) {
            double s2 = B[r];
            #pragma unroll
            for (int k = 0; k < r; k++) s2 -= L[LT(r, k)] * B[k];
            B[r] = s2 / L[LT(r, r)];
        }
        // Back solve L^T w = z    (in place in B)
        #pragma unroll
        for (int c = KD - 1; c >= 0; c--) {
            double s2 = B[c];
            #pragma unroll
            for (int k = c + 1; k < KD; k++) s2 -= L[LT(k, c)] * B[k];
            B[c] = s2 / L[LT(c, c)];
        }
    }
    __syncwarp();

    if (lane < KD) g_w[row * 8 + lane] = (float)shB[warp][lane];
}

// ============================================================
// Kernel B: streaming emit (coeffs, logits, hard, x_hat)
// Low-reg, high-occupancy, store-bound.
// ============================================================
__global__ __launch_bounds__(256)
void emit_kernel(const float* __restrict__ x, float* __restrict__ out, int N) {
    __shared__ float s[SEQ];
    __shared__ float wf[8];

    const int row = blockIdx.x;
    const int tid = threadIdx.x;

    if (tid < 150)
        ((float4*)s)[tid] = ((const float4*)(x + (size_t)row * SEQ))[tid];
    if (tid < KD)
        wf[tid] = g_w[row * 8 + tid];
    __syncthreads();

    const size_t Ns = (size_t)N;
    float* coeffs = out;
    float* plog   = out + Ns * 3600;
    int*   phard  = (int*)(out + Ns * 3605);
    float* xhat   = out + Ns * 3606;

    // ---- coeffs: repeating [w1..w6] pattern (period 3 in float4) ----
    const float4 p0 = make_float4(wf[1], wf[2], wf[3], wf[4]);
    const float4 p1 = make_float4(wf[5], wf[6], wf[1], wf[2]);
    const float4 p2 = make_float4(wf[3], wf[4], wf[5], wf[6]);
    const float4 z4 = make_float4(0.f, 0.f, 0.f, 0.f);
    float4* cv = (float4*)(coeffs + (size_t)row * 3600);
    #pragma unroll
    for (int i = 0; i < 4; i++) {
        int j = tid + i * 256;
        if (j < 900) {
            float4 v;
            if (j < 9) {
                v = z4;                 // t < 6 -> masked to zero
            } else {
                int m = j % 3;
                v = (m == 0) ? p0 : ((m == 1) ? p1 : p2);
            }
            cv[j] = v;
        }
    }

    // ---- p_logits / p_hard: zeros ----
    if (tid < 5) plog[(size_t)row * 5 + tid] = 0.f;
    if (tid == 5) phard[row] = 0;

    // ---- x_hat: 0 for t<6, else w0 + sum w[k]*x[t-k] ----
    if (tid < 150) {
        const float w0 = wf[0], w1 = wf[1], w2 = wf[2], w3 = wf[3],
                    w4 = wf[4], w5 = wf[5], w6 = wf[6];
        float4 v;
        const int t0 = tid * 4;
        float* vc = (float*)&v;
        #pragma unroll
        for (int c = 0; c < 4; c++) {
            const int t = t0 + c;
            float p = 0.f;
            if (t >= PP) {
                p = w0;
                p = fmaf(w1, s[t - 1], p);
                p = fmaf(w2, s[t - 2], p);
                p = fmaf(w3, s[t - 3], p);
                p = fmaf(w4, s[t - 4], p);
                p = fmaf(w5, s[t - 5], p);
                p = fmaf(w6, s[t - 6], p);
            }
            vc[c] = p;
        }
        ((float4*)(xhat + (size_t)row * SEQ))[tid] = v;
    }
}

extern "C" void kernel_launch(void* const* d_in, const int* in_sizes, int n_in,
                              void* d_out, int out_size) {
    const float* x = (const float*)d_in[0];
    const int N = in_sizes[0] / SEQ;
    float* out = (float*)d_out;

    const int blocksA = (N + NWA - 1) / NWA;
    solve_kernel<<<blocksA, NWA * 32>>>(x, N);
    emit_kernel<<<N, 256>>>(x, out, N);
}

// round 3
// speedup vs baseline: 2.4741x; 2.4741x over previous
#include <cuda_runtime.h>

#define SEQ   600
#define TOUT  594   // SEQ - P
#define PP    6
#define KD    7

// lower-triangular index, r >= c
#define LT(r, c) ((r) * ((r) + 1) / 2 + (c))
// upper-tri (k<=l) packed index used by G accumulation
#define GU(k, l) ((k) * KD - (k) * ((k) - 1) / 2 + ((l) - (k)))

__global__ __launch_bounds__(256)
void ar_fused(const float* __restrict__ x, float* __restrict__ out, int N) {
    __shared__ float s[SEQ + 8];
    __shared__ float red[8][40];   // per-warp partials of 35 sums (padded rows)
    __shared__ float gtot[35];     // block totals: G[28] then b[7]
    __shared__ float wf[8];        // solved weights

    const int row  = blockIdx.x;
    const int tid  = threadIdx.x;
    const int lane = tid & 31;
    const int warp = tid >> 5;

    // ---- Load row (600 floats = 150 float4), coalesced ----
    if (tid < 150)
        ((float4*)s)[tid] = ((const float4*)(x + (size_t)row * SEQ))[tid];
    __syncthreads();

    // ---- Accumulate G (28 upper-tri) and b (7), fp32, strided over block ----
    float G[28], bb[KD];
    #pragma unroll
    for (int i = 0; i < 28; i++) G[i] = 0.f;
    #pragma unroll
    for (int i = 0; i < KD; i++) bb[i] = 0.f;

    for (int t = tid; t < TOUT; t += 256) {
        float d[KD];
        d[0] = 1.f;
        d[1] = s[t + 5];
        d[2] = s[t + 4];
        d[3] = s[t + 3];
        d[4] = s[t + 2];
        d[5] = s[t + 1];
        d[6] = s[t + 0];
        const float y = s[t + 6];
        int idx = 0;
        #pragma unroll
        for (int k = 0; k < KD; k++) {
            #pragma unroll
            for (int l = k; l < KD; l++) {
                G[idx] = fmaf(d[k], d[l], G[idx]);
                idx++;
            }
            bb[k] = fmaf(d[k], y, bb[k]);
        }
    }

    // ---- Warp butterfly reduction of 35 values ----
    #pragma unroll
    for (int i = 0; i < 28; i++) {
        #pragma unroll
        for (int o = 16; o > 0; o >>= 1)
            G[i] += __shfl_xor_sync(0xffffffffu, G[i], o);
    }
    #pragma unroll
    for (int i = 0; i < KD; i++) {
        #pragma unroll
        for (int o = 16; o > 0; o >>= 1)
            bb[i] += __shfl_xor_sync(0xffffffffu, bb[i], o);
    }

    // lane 0 of each warp publishes partials
    if (lane == 0) {
        #pragma unroll
        for (int i = 0; i < 28; i++) red[warp][i] = G[i];
        #pragma unroll
        for (int i = 0; i < KD; i++) red[warp][28 + i] = bb[i];
    }
    __syncthreads();

    // ---- Cross-warp reduce: threads 0..34 sum 8 partials ----
    if (tid < 35) {
        float tot = 0.f;
        #pragma unroll
        for (int w = 0; w < 8; w++) tot += red[w][tid];
        gtot[tid] = tot;
    }
    __syncthreads();

    // ---- Thread 0: fp32 Cholesky solve, fully in registers ----
    if (tid == 0) {
        float L[28], B[KD];
        // A(lower)[r][c] = G(c, r) for r >= c
        #pragma unroll
        for (int c = 0; c < KD; c++)
            #pragma unroll
            for (int r = c; r < KD; r++)
                L[LT(r, c)] = gtot[GU(c, r)];
        #pragma unroll
        for (int k = 0; k < KD; k++) B[k] = gtot[28 + k];

        // Cholesky: L <- chol(A)
        #pragma unroll
        for (int c = 0; c < KD; c++) {
            float sd = L[LT(c, c)];
            #pragma unroll
            for (int k = 0; k < c; k++) sd = fmaf(-L[LT(c, k)], L[LT(c, k)], sd);
            float lcc = sqrtf(sd);
            L[LT(c, c)] = lcc;
            float inv = 1.0f / lcc;
            #pragma unroll
            for (int r = c + 1; r < KD; r++) {
                float s2 = L[LT(r, c)];
                #pragma unroll
                for (int k = 0; k < c; k++) s2 = fmaf(-L[LT(r, k)], L[LT(c, k)], s2);
                L[LT(r, c)] = s2 * inv;
            }
        }
        // Forward solve L z = b (in place in B)
        #pragma unroll
        for (int r = 0; r < KD; r++) {
            float s2 = B[r];
            #pragma unroll
            for (int k = 0; k < r; k++) s2 = fmaf(-L[LT(r, k)], B[k], s2);
            B[r] = s2 / L[LT(r, r)];
        }
        // Back solve L^T w = z (in place in B)
        #pragma unroll
        for (int c = KD - 1; c >= 0; c--) {
            float s2 = B[c];
            #pragma unroll
            for (int k = c + 1; k < KD; k++) s2 = fmaf(-L[LT(k, c)], B[k], s2);
            B[c] = s2 / L[LT(c, c)];
        }
        #pragma unroll
        for (int k = 0; k < KD; k++) wf[k] = B[k];
    }
    __syncthreads();

    // ---- Output layout (flat, reference tuple order) ----
    const size_t Ns = (size_t)N;
    float* coeffs = out;
    float* plog   = out + Ns * 3600;
    int*   phard  = (int*)(out + Ns * 3605);
    float* xhat   = out + Ns * 3606;

    const float w0 = wf[0], w1 = wf[1], w2 = wf[2], w3 = wf[3],
                w4 = wf[4], w5 = wf[5], w6 = wf[6];

    // ---- coeffs: repeating [w1..w6] pattern (period 3 in float4) ----
    const float4 p0 = make_float4(w1, w2, w3, w4);
    const float4 p1 = make_float4(w5, w6, w1, w2);
    const float4 p2 = make_float4(w3, w4, w5, w6);
    const float4 z4 = make_float4(0.f, 0.f, 0.f, 0.f);
    float4* cv = (float4*)(coeffs + (size_t)row * 3600);
    #pragma unroll
    for (int i = 0; i < 4; i++) {
        int j = tid + i * 256;
        if (j < 900) {
            float4 v;
            if (j < 9) {
                v = z4;                 // t < 6 -> masked to zero
            } else {
                int m = j % 3;
                v = (m == 0) ? p0 : ((m == 1) ? p1 : p2);
            }
            cv[j] = v;
        }
    }

    // ---- p_logits / p_hard: zeros ----
    if (tid < 5) plog[(size_t)row * 5 + tid] = 0.f;
    if (tid == 5) phard[row] = 0;

    // ---- x_hat: 0 for t<6, else w0 + sum w[k]*x[t-k] ----
    if (tid < 150) {
        float4 v;
        float* vc = (float*)&v;
        const int t0 = tid * 4;
        #pragma unroll
        for (int c = 0; c < 4; c++) {
            const int t = t0 + c;
            float p = 0.f;
            if (t >= PP) {
                p = w0;
                p = fmaf(w1, s[t - 1], p);
                p = fmaf(w2, s[t - 2], p);
                p = fmaf(w3, s[t - 3], p);
                p = fmaf(w4, s[t - 4], p);
                p = fmaf(w5, s[t - 5], p);
                p = fmaf(w6, s[t - 6], p);
            }
            vc[c] = p;
        }
        ((float4*)(xhat + (size_t)row * SEQ))[tid] = v;
    }
}

extern "C" void kernel_launch(void* const* d_in, const int* in_sizes, int n_in,
                              void* d_out, int out_size) {
    const float* x = (const float*)d_in[0];
    const int N = in_sizes[0] / SEQ;
    float* out = (float*)d_out;
    ar_fused<<<N, 256>>>(x, out, N);
}

// round 4
// speedup vs baseline: 5.7593x; 2.3278x over previous
#include <cuda_runtime.h>

#define SEQ   600
#define PP    6
#define KD    7
#define NW    8      // warps (rows) per block
#define CH    19     // contiguous u-chunk per lane (19*32 = 608 >= 600)

// lower-triangular index, r >= c
#define LT(r, c) ((r) * ((r) + 1) / 2 + (c))

__global__ __launch_bounds__(NW * 32)
void ar_warp(const float* __restrict__ x, float* __restrict__ out, int N) {
    __shared__ float sh[NW][SEQ + 8];

    const int warp = threadIdx.x >> 5;
    const int lane = threadIdx.x & 31;
    const int row  = blockIdx.x * NW + warp;
    if (row >= N) return;

    // ---- Load row (150 float4) into shared, coalesced ----
    const float4* xv = (const float4*)(x + (size_t)row * SEQ);
    float4* sv = (float4*)sh[warp];
    #pragma unroll
    for (int i = 0; i < 5; i++) {
        int j = lane + i * 32;
        if (j < 150) sv[j] = xv[j];
    }
    __syncwarp();
    const float* s = sh[warp];

    // ---- Autocorrelations C_j = sum_u x[u]*x[u+j] (j=0..6) and S = sum x ----
    // Each lane owns contiguous u in [19*lane, 19*lane+19), sliding window in regs.
    float C[7] = {0.f, 0.f, 0.f, 0.f, 0.f, 0.f, 0.f};
    float S = 0.f;
    const int u0 = lane * CH;
    float r6[6];   // holds x[u-6..u-1]
    #pragma unroll
    for (int i = 0; i < 6; i++) {
        int idx = u0 - 6 + i;
        r6[i] = (idx >= 0) ? s[idx] : 0.f;
    }
    #pragma unroll
    for (int i = 0; i < CH; i++) {
        const int u = u0 + i;
        if (u < SEQ) {
            const float v = s[u];
            S += v;
            C[0] = fmaf(v, v,     C[0]);
            C[1] = fmaf(v, r6[5], C[1]);
            C[2] = fmaf(v, r6[4], C[2]);
            C[3] = fmaf(v, r6[3], C[3]);
            C[4] = fmaf(v, r6[2], C[4]);
            C[5] = fmaf(v, r6[1], C[5]);
            C[6] = fmaf(v, r6[0], C[6]);
            r6[0] = r6[1]; r6[1] = r6[2]; r6[2] = r6[3];
            r6[3] = r6[4]; r6[4] = r6[5]; r6[5] = v;
        }
    }

    // ---- Warp butterfly reduction of 8 values ----
    #pragma unroll
    for (int j = 0; j < 7; j++) {
        #pragma unroll
        for (int o = 16; o > 0; o >>= 1)
            C[j] += __shfl_xor_sync(0xffffffffu, C[j], o);
    }
    #pragma unroll
    for (int o = 16; o > 0; o >>= 1)
        S += __shfl_xor_sync(0xffffffffu, S, o);

    // ---- Lane 0: edge corrections -> G,b ; fp32 Cholesky solve ----
    float wf[KD];
    if (lane == 0) {
        float h[11], tl[6];
        #pragma unroll
        for (int i = 0; i < 11; i++) h[i] = s[i];
        #pragma unroll
        for (int i = 0; i < 6; i++)  tl[i] = s[594 + i];

        float A[28], B[KD];
        A[LT(0, 0)] = 594.f;
        // First column: G[1+a][0] = S - head - tail
        #pragma unroll
        for (int a = 0; a < 6; a++) {
            float hs = 0.f, ts = 0.f;
            #pragma unroll
            for (int u = 0; u <= 4; u++) if (u <= 4 - a) hs += h[u];
            #pragma unroll
            for (int i = 0; i <= 5; i++) if (i <= a) ts += tl[5 - a + i];
            A[LT(1 + a, 0)] = S - hs - ts;
        }
        // Interior: G[1+a][1+b] = C[a-b] - head - tail   (a >= b)
        #pragma unroll
        for (int a = 0; a < 6; a++) {
            #pragma unroll
            for (int b = 0; b <= a; b++) {
                float hs = 0.f, ts = 0.f;
                #pragma unroll
                for (int u = 0; u <= 4; u++)
                    if (u <= 4 - a) hs = fmaf(h[u], h[u + a - b], hs);
                #pragma unroll
                for (int i = 0; i <= 5; i++)
                    if (i <= b) ts = fmaf(tl[5 - a + i], tl[5 - b + i], ts);
                A[LT(1 + a, 1 + b)] = C[a - b] - hs - ts;
            }
        }
        // rhs
        B[0] = S - (h[0] + h[1] + h[2] + h[3] + h[4] + h[5]);
        #pragma unroll
        for (int a = 0; a < 6; a++) {
            float hs = 0.f;
            #pragma unroll
            for (int u = 0; u <= 4; u++)
                if (u <= 4 - a) hs = fmaf(h[u], h[u + a + 1], hs);
            B[1 + a] = C[a + 1] - hs;
        }

        // Cholesky: A(lower) <- L
        #pragma unroll
        for (int c = 0; c < KD; c++) {
            float sd = A[LT(c, c)];
            #pragma unroll
            for (int k = 0; k < c; k++) sd = fmaf(-A[LT(c, k)], A[LT(c, k)], sd);
            float lcc = sqrtf(sd);
            A[LT(c, c)] = lcc;
            float inv = 1.0f / lcc;
            #pragma unroll
            for (int r = c + 1; r < KD; r++) {
                float s2 = A[LT(r, c)];
                #pragma unroll
                for (int k = 0; k < c; k++) s2 = fmaf(-A[LT(r, k)], A[LT(c, k)], s2);
                A[LT(r, c)] = s2 * inv;
            }
        }
        // Forward solve L z = b (in place)
        #pragma unroll
        for (int r = 0; r < KD; r++) {
            float s2 = B[r];
            #pragma unroll
            for (int k = 0; k < r; k++) s2 = fmaf(-A[LT(r, k)], B[k], s2);
            B[r] = s2 / A[LT(r, r)];
        }
        // Back solve L^T w = z (in place)
        #pragma unroll
        for (int c = KD - 1; c >= 0; c--) {
            float s2 = B[c];
            #pragma unroll
            for (int k = c + 1; k < KD; k++) s2 = fmaf(-A[LT(k, c)], B[k], s2);
            B[c] = s2 / A[LT(c, c)];
        }
        #pragma unroll
        for (int k = 0; k < KD; k++) wf[k] = B[k];
    }
    #pragma unroll
    for (int j = 0; j < KD; j++)
        wf[j] = __shfl_sync(0xffffffffu, wf[j], 0);

    // ---- Output layout (flat, reference tuple order) ----
    const size_t Ns = (size_t)N;
    float* coeffs = out;
    float* plog   = out + Ns * 3600;
    int*   phard  = (int*)(out + Ns * 3605);
    float* xhat   = out + Ns * 3606;

    const float w0 = wf[0], w1 = wf[1], w2 = wf[2], w3 = wf[3],
                w4 = wf[4], w5 = wf[5], w6 = wf[6];

    // ---- coeffs: repeating [w1..w6] pattern (period 3 in float4) ----
    const float4 p0 = make_float4(w1, w2, w3, w4);
    const float4 p1 = make_float4(w5, w6, w1, w2);
    const float4 p2 = make_float4(w3, w4, w5, w6);
    const float4 z4 = make_float4(0.f, 0.f, 0.f, 0.f);
    float4* cv = (float4*)(coeffs + (size_t)row * 3600);
    #pragma unroll
    for (int k = 0; k < 29; k++) {
        const int j = lane + k * 32;
        if (j < 900) {
            float4 v;
            if (j < 9) {
                v = z4;                 // t < 6 -> masked to zero
            } else {
                const int m = j % 3;
                v = (m == 0) ? p0 : ((m == 1) ? p1 : p2);
            }
            cv[j] = v;
        }
    }

    // ---- p_logits / p_hard: zeros ----
    if (lane < 5) plog[(size_t)row * 5 + lane] = 0.f;
    if (lane == 5) phard[row] = 0;

    // ---- x_hat: 0 for t<6, else w0 + sum w[k]*x[t-k] ----
    float4* hv = (float4*)(xhat + (size_t)row * SEQ);
    #pragma unroll
    for (int k = 0; k < 5; k++) {
        const int i = lane + k * 32;
        if (i < 150) {
            float4 v;
            float* vc = (float*)&v;
            const int t0 = i * 4;
            #pragma unroll
            for (int c = 0; c < 4; c++) {
                const int t = t0 + c;
                float p = 0.f;
                if (t >= PP) {
                    p = w0;
                    p = fmaf(w1, s[t - 1], p);
                    p = fmaf(w2, s[t - 2], p);
                    p = fmaf(w3, s[t - 3], p);
                    p = fmaf(w4, s[t - 4], p);
                    p = fmaf(w5, s[t - 5], p);
                    p = fmaf(w6, s[t - 6], p);
                }
                vc[c] = p;
            }
            hv[i] = v;
        }
    }
}

extern "C" void kernel_launch(void* const* d_in, const int* in_sizes, int n_in,
                              void* d_out, int out_size) {
    const float* x = (const float*)d_in[0];
    const int N = in_sizes[0] / SEQ;
    float* out = (float*)d_out;
    const int blocks = (N + NW - 1) / NW;
    ar_warp<<<blocks, NW * 32>>>(x, out, N);
}